// round 10
// baseline (speedup 1.0000x reference)
#include <cuda_runtime.h>
#include <cuda_bf16.h>
#include <math.h>
#include <stdint.h>

#define NMAX 50000
#define EMAX 800000
#define ETOTAL (EMAX + NMAX)
#define IN_DIM 256
#define HID 64
#define L1C 256
#define OUTD 64
#define SCAN_BLK 1024
#define NSCAN ((NMAX + SCAN_BLK - 1) / SCAN_BLK)

// legacy mma GEMM (layer 2): 3 stages x 4 arrays x 128 x 24 bf16
#define GEMM_STAGE_ELEMS (4 * 128 * 24)
#define GEMM_SMEM_BYTES (3 * GEMM_STAGE_ELEMS * 2)

// A-resident GEMM1: A hi/lo [16 chunks][128 rows][16 cols] = 65536 elems (128KB)
// + B ring 3 stages x (hi|lo) x [128][24] = 3*6144 elems (36KB)
#define G1_A_ELEMS (2 * 16 * 128 * 16)
#define G1_B_STAGE 6144
#define G1_SMEM_BYTES ((G1_A_ELEMS + 3 * G1_B_STAGE) * 2)

// ---------------- scratch (device globals; allocation-free) ----------------
__device__ float g_xl1[(size_t)NMAX * L1C];
__device__ float g_xr1[(size_t)NMAX * L1C];   // reused for layer2 xl2/xr2
__device__ float g_h[(size_t)NMAX * HID];
__device__ __nv_bfloat16 g_ahi[(size_t)NMAX * 256];
__device__ __nv_bfloat16 g_alo[(size_t)NMAX * 256];
__device__ __nv_bfloat16 g_bhi[512 * 256];
__device__ __nv_bfloat16 g_blo[512 * 256];
__device__ __nv_bfloat16 g_bhi2[128 * 64];
__device__ __nv_bfloat16 g_blo2[128 * 64];
__device__ int   g_deg[NMAX + 1];
__device__ int   g_off[NMAX + 1];
__device__ int   g_cur[NMAX];
__device__ int   g_src[ETOTAL];
__device__ int   g_bsum[NSCAN + 1];

// ---------------- CSR build ----------------
__global__ void zero_deg_kernel(int n) {
    int i = blockIdx.x * blockDim.x + threadIdx.x;
    if (i <= n) g_deg[i] = 0;
}

__global__ void hist_kernel(const int* __restrict__ ei, int E, int n) {
    int e = blockIdx.x * blockDim.x + threadIdx.x;
    int tot = E + n;
    if (e < tot) {
        int d = (e < E) ? ei[E + e] : (e - E);
        if (d < 0) d = 0;
        if (d >= n) d = n - 1;
        atomicAdd(&g_deg[d], 1);
    }
}

__global__ void scan1_kernel(int n) {
    __shared__ int sh[SCAN_BLK];
    int tid = threadIdx.x;
    int idx = blockIdx.x * SCAN_BLK + tid;
    int v = (idx < n) ? g_deg[idx] : 0;
    sh[tid] = v;
    __syncthreads();
    for (int d = 1; d < SCAN_BLK; d <<= 1) {
        int t = sh[tid];
        int add = (tid >= d) ? sh[tid - d] : 0;
        __syncthreads();
        sh[tid] = t + add;
        __syncthreads();
    }
    if (idx < n) g_off[idx] = sh[tid] - v;
    if (tid == SCAN_BLK - 1) g_bsum[blockIdx.x] = sh[tid];
}

__global__ void scan2_kernel(int nb, int n) {
    __shared__ int wsum[2];
    int t = threadIdx.x;
    int w = t >> 5, l = t & 31;
    int v = (t < nb) ? g_bsum[t] : 0;
    int sc = v;
#pragma unroll
    for (int d = 1; d < 32; d <<= 1) {
        int u = __shfl_up_sync(0xffffffffu, sc, d);
        if (l >= d) sc += u;
    }
    if (l == 31) wsum[w] = sc;
    __syncthreads();
    int base = (w == 1) ? wsum[0] : 0;
    if (t < nb) g_bsum[t] = sc - v + base;
    if (t == 0) {
        int tot = wsum[0] + ((nb > 32) ? wsum[1] : 0);
        if (nb <= 32) tot = wsum[0];
        g_off[n] = tot;
    }
}

__global__ void scan3_kernel(int n) {
    int idx = blockIdx.x * SCAN_BLK + threadIdx.x;
    if (idx < n) {
        int o = g_off[idx] + g_bsum[blockIdx.x];
        g_off[idx] = o;
        g_cur[idx] = o;
    }
}

__global__ void scatter_kernel(const int* __restrict__ ei, int E, int n) {
    int e = blockIdx.x * blockDim.x + threadIdx.x;
    int tot = E + n;
    if (e < tot) {
        int s, d;
        if (e < E) { s = ei[e]; d = ei[E + e]; }
        else       { s = d = e - E; }
        if (s < 0) s = 0; if (s >= n) s = n - 1;
        if (d < 0) d = 0; if (d >= n) d = n - 1;
        int pos = atomicAdd(&g_cur[d], 1);
        if (pos >= 0 && pos < ETOTAL) g_src[pos] = s;
    }
}

// ---------------- fp32 -> (hi, lo) bf16 split ----------------
__global__ void conv_split_kernel(const float* __restrict__ in,
                                  __nv_bfloat16* __restrict__ hi,
                                  __nv_bfloat16* __restrict__ lo, int n4) {
    int i = blockIdx.x * blockDim.x + threadIdx.x;
    if (i < n4) {
        float4 v = ((const float4*)in)[i];
        __nv_bfloat16 h0 = __float2bfloat16(v.x);
        __nv_bfloat16 h1 = __float2bfloat16(v.y);
        __nv_bfloat16 h2 = __float2bfloat16(v.z);
        __nv_bfloat16 h3 = __float2bfloat16(v.w);
        __nv_bfloat162 hh0{h0, h1}, hh1{h2, h3};
        ((__nv_bfloat162*)hi)[2 * i] = hh0;
        ((__nv_bfloat162*)hi)[2 * i + 1] = hh1;
        __nv_bfloat162 ll0{__float2bfloat16(v.x - __bfloat162float(h0)),
                           __float2bfloat16(v.y - __bfloat162float(h1))};
        __nv_bfloat162 ll1{__float2bfloat16(v.z - __bfloat162float(h2)),
                           __float2bfloat16(v.w - __bfloat162float(h3))};
        ((__nv_bfloat162*)lo)[2 * i] = ll0;
        ((__nv_bfloat162*)lo)[2 * i + 1] = ll1;
    }
}

// ---------------- pack Wl|Wr -> Bt[n][k] (transposed), hi/lo split ----------
__global__ void pack_bt_kernel(const float* __restrict__ Wl, const float* __restrict__ Wr,
                               __nv_bfloat16* __restrict__ bhi, __nv_bfloat16* __restrict__ blo,
                               int K, int Nhalf) {
    int idx = blockIdx.x * blockDim.x + threadIdx.x;
    int tot = 2 * Nhalf * K;
    if (idx < tot) {
        int n = idx / K, k = idx % K;
        float v = (n < Nhalf) ? Wl[(size_t)k * Nhalf + n] : Wr[(size_t)k * Nhalf + (n - Nhalf)];
        __nv_bfloat16 h = __float2bfloat16(v);
        bhi[idx] = h;
        blo[idx] = __float2bfloat16(v - __bfloat162float(h));
    }
}

// ---------------- async copy + ldmatrix + mma helpers ----------------
__device__ __forceinline__ void cp16(void* sdst, const void* gsrc, int src_bytes) {
    uint32_t s = (uint32_t)__cvta_generic_to_shared(sdst);
    asm volatile("cp.async.cg.shared.global [%0], [%1], 16, %2;\n"
                 :: "r"(s), "l"(gsrc), "r"(src_bytes));
}
__device__ __forceinline__ void cp_commit() { asm volatile("cp.async.commit_group;\n"); }
__device__ __forceinline__ void cp_wait1() { asm volatile("cp.async.wait_group 1;\n"); }
__device__ __forceinline__ void cp_wait0() { asm volatile("cp.async.wait_group 0;\n"); }

__device__ __forceinline__ void ldsm4(uint32_t r[4], const void* p) {
    uint32_t a = (uint32_t)__cvta_generic_to_shared(p);
    asm volatile("ldmatrix.sync.aligned.m8n8.x4.shared.b16 {%0,%1,%2,%3}, [%4];\n"
                 : "=r"(r[0]), "=r"(r[1]), "=r"(r[2]), "=r"(r[3]) : "r"(a));
}

__device__ __forceinline__ void mma_bf16(float d[4], const uint32_t a[4], const uint32_t b[2]) {
    asm volatile(
        "mma.sync.aligned.m16n8k16.row.col.f32.bf16.bf16.f32 "
        "{%0,%1,%2,%3}, {%4,%5,%6,%7}, {%8,%9}, {%0,%1,%2,%3};\n"
        : "+f"(d[0]), "+f"(d[1]), "+f"(d[2]), "+f"(d[3])
        : "r"(a[0]), "r"(a[1]), "r"(a[2]), "r"(a[3]), "r"(b[0]), "r"(b[1]));
}

// A-smem swizzled element offset for (row, u16) within one chunk.
// chunk layout: 128 rows x 16 cols bf16, as 16B units; unit = row*2 + (u ^ ((row>>2)&1))
__device__ __forceinline__ uint32_t a_sw(int row, int u) {
    return (uint32_t)((row * 2 + (u ^ ((row >> 2) & 1))) * 8);
}

// ---- GEMM1 (A-resident): C[M,512] = A[M,256](hi/lo) x Bt[512,256](hi/lo) ----
// One CTA: 128 rows x all 512 cols. A full-K in smem (loaded once), B streamed.
__global__ __launch_bounds__(256, 1)
void gemm1_ares_kernel(const __nv_bfloat16* __restrict__ Ahi, const __nv_bfloat16* __restrict__ Alo,
                       const __nv_bfloat16* __restrict__ Bhi, const __nv_bfloat16* __restrict__ Blo,
                       float* __restrict__ C0, float* __restrict__ C1, int M) {
    extern __shared__ __nv_bfloat16 sm[];
    __nv_bfloat16* Ahi_s = sm;                       // [16][128][16] swizzled
    __nv_bfloat16* Alo_s = sm + 32768;
    __nv_bfloat16* Bring = sm + G1_A_ELEMS;          // 3 stages x (hi [128][24] | lo [128][24])

    int t = threadIdx.x;
    int lane = t & 31, wid = t >> 5;
    int wm = wid & 1, wn = wid >> 1;                 // 2 x 4 warp grid (64x32 warp tiles)
    int group = lane >> 2, tig = lane & 3;
    int m0 = blockIdx.x * 128;

    // ---- A prologue: 32 cp16 per thread, one commit group ----
    int arow = t >> 1;              // 0..127
    int au = t & 1;                 // 16B unit within 16-col chunk row
    int grow = m0 + arow;
    int abytes = (grow < M) ? 16 : 0;
    const __nv_bfloat16* gAhi = Ahi + (size_t)(grow < M ? grow : 0) * 256 + au * 8;
    const __nv_bfloat16* gAlo = Alo + (size_t)(grow < M ? grow : 0) * 256 + au * 8;
    uint32_t aoff = a_sw(arow, au);
#pragma unroll
    for (int c = 0; c < 16; c++) {
        cp16(Ahi_s + c * 2048 + aoff, gAhi + c * 16, abytes);
        cp16(Alo_s + c * 2048 + aoff, gAlo + c * 16, abytes);
    }
    cp_commit();

    // ---- B loader: stage g covers n-tile (g>>4), k-chunk (g&15) ----
    int lrow = t >> 1, lkq = (t & 1) * 8;
    auto load_B = [&](int g) {
        __nv_bfloat16* st = Bring + (g % 3) * G1_B_STAGE;
        const __nv_bfloat16* ph = Bhi + (size_t)((g >> 4) * 128 + lrow) * 256 + (g & 15) * 16 + lkq;
        const __nv_bfloat16* pl = Blo + (size_t)((g >> 4) * 128 + lrow) * 256 + (g & 15) * 16 + lkq;
        cp16(st + lrow * 24 + lkq, ph, 16);
        cp16(st + 3072 + lrow * 24 + lkq, pl, 16);
        cp_commit();
    };
    load_B(0);
    load_B(1);

    // ldsm lane address components
    int a_lrow = lane & 15;
    int a_lu = (lane >> 4) & 1;
    int b_row = ((lane >> 4) & 1) * 8 + (lane & 7);
    int b_col = ((lane >> 3) & 1) * 8;

    float acc[4][4][4];
#pragma unroll
    for (int i = 0; i < 4; i++)
#pragma unroll
        for (int j = 0; j < 4; j++)
#pragma unroll
            for (int q = 0; q < 4; q++) acc[i][j][q] = 0.f;

    for (int g = 0; g < 64; g++) {
        if (g + 1 < 64) cp_wait1(); else cp_wait0();
        __syncthreads();
        if (g + 2 < 64) load_B(g + 2);

        int c = g & 15;
        __nv_bfloat16* st = Bring + (g % 3) * G1_B_STAGE;

        uint32_t a_hi[4][4], a_lo[4][4];
#pragma unroll
        for (int mf = 0; mf < 4; mf++) {
            int row = wm * 64 + mf * 16 + a_lrow;
            uint32_t off = c * 2048 + a_sw(row, a_lu);
            ldsm4(a_hi[mf], Ahi_s + off);
            ldsm4(a_lo[mf], Alo_s + off);
        }
        uint32_t b_hi[2][4], b_lo[2][4];
#pragma unroll
        for (int p = 0; p < 2; p++) {
            int c0 = wn * 32 + p * 16;
            ldsm4(b_hi[p], st + (c0 + b_row) * 24 + b_col);
            ldsm4(b_lo[p], st + 3072 + (c0 + b_row) * 24 + b_col);
        }
#pragma unroll
        for (int nf = 0; nf < 4; nf++) {
            const uint32_t* bh = &b_hi[nf >> 1][(nf & 1) * 2];
            const uint32_t* bl = &b_lo[nf >> 1][(nf & 1) * 2];
#pragma unroll
            for (int mf = 0; mf < 4; mf++) {
                mma_bf16(acc[mf][nf], a_hi[mf], bh);
                mma_bf16(acc[mf][nf], a_hi[mf], bl);
                mma_bf16(acc[mf][nf], a_lo[mf], bh);
            }
        }

        if (c == 15) {
            // epilogue for n-tile (g>>4), then reset accumulators
            int n0 = (g >> 4) * 128;
#pragma unroll
            for (int mf = 0; mf < 4; mf++) {
                int r = m0 + wm * 64 + mf * 16 + group;
#pragma unroll
                for (int nf = 0; nf < 4; nf++) {
                    int cc = n0 + wn * 32 + nf * 8 + tig * 2;
                    float* dst = C0;
                    int ccol = cc;
                    if (cc >= 256) { dst = C1; ccol = cc - 256; }
                    if (r < M)
                        *(float2*)&dst[(size_t)r * 256 + ccol] =
                            make_float2(acc[mf][nf][0], acc[mf][nf][1]);
                    if (r + 8 < M)
                        *(float2*)&dst[(size_t)(r + 8) * 256 + ccol] =
                            make_float2(acc[mf][nf][2], acc[mf][nf][3]);
                    acc[mf][nf][0] = 0.f; acc[mf][nf][1] = 0.f;
                    acc[mf][nf][2] = 0.f; acc[mf][nf][3] = 0.f;
                }
            }
        }
    }
}

// ---- legacy mma.sync GEMM (layer 2), 3-stage cp.async ----
template <int KCHUNKS>
__global__ __launch_bounds__(256, 2)
void mma_gemm_kernel(const __nv_bfloat16* __restrict__ Ahi, const __nv_bfloat16* __restrict__ Alo,
                     const __nv_bfloat16* __restrict__ Bhi, const __nv_bfloat16* __restrict__ Blo,
                     float* __restrict__ C0, float* __restrict__ C1,
                     int M, int ncut, int ld) {
    constexpr int K = KCHUNKS * 16;
    extern __shared__ __nv_bfloat16 sm[];
    __nv_bfloat16* stage_base[3] = { sm, sm + GEMM_STAGE_ELEMS, sm + 2 * GEMM_STAGE_ELEMS };

    int t = threadIdx.x;
    int lane = t & 31, wid = t >> 5;
    int wm = wid & 1, wn = wid >> 1;
    int group = lane >> 2, tig = lane & 3;
    int m0 = blockIdx.y * 128, n0 = blockIdx.x * 128;

    int a_row = lane & 15;
    int a_col = ((lane >> 4) & 1) * 8;
    int b_row = ((lane >> 4) & 1) * 8 + (lane & 7);
    int b_col = ((lane >> 3) & 1) * 8;

    float acc[4][4][4];
#pragma unroll
    for (int i = 0; i < 4; i++)
#pragma unroll
        for (int j = 0; j < 4; j++)
#pragma unroll
            for (int q = 0; q < 4; q++) acc[i][j][q] = 0.f;

    int lrow = t >> 1, lkq = (t & 1) * 8;
    int grow = m0 + lrow;
    int abytes = (grow < M) ? 16 : 0;
    const __nv_bfloat16* pAhi = Ahi + (size_t)(grow < M ? grow : 0) * K + lkq;
    const __nv_bfloat16* pAlo = Alo + (size_t)(grow < M ? grow : 0) * K + lkq;
    const __nv_bfloat16* pBhi = Bhi + (size_t)(n0 + lrow) * K + lkq;
    const __nv_bfloat16* pBlo = Blo + (size_t)(n0 + lrow) * K + lkq;
    int lofs = lrow * 24 + lkq;

    auto load_stage = [&](int c, int st) {
        __nv_bfloat16* base = stage_base[st];
        int ko = c * 16;
        cp16(base + lofs,        pAhi + ko, abytes);
        cp16(base + 3072 + lofs, pAlo + ko, abytes);
        cp16(base + 6144 + lofs, pBhi + ko, 16);
        cp16(base + 9216 + lofs, pBlo + ko, 16);
        cp_commit();
    };

    load_stage(0, 0);
    if (KCHUNKS > 1) load_stage(1, 1);

#pragma unroll
    for (int c = 0; c < KCHUNKS; c++) {
        if (c + 1 < KCHUNKS) cp_wait1(); else cp_wait0();
        __syncthreads();
        if (c + 2 < KCHUNKS) load_stage(c + 2, (c + 2) % 3);

        __nv_bfloat16* base = stage_base[c % 3];
        __nv_bfloat16* as_hi = base;
        __nv_bfloat16* as_lo = base + 3072;
        __nv_bfloat16* bs_hi = base + 6144;
        __nv_bfloat16* bs_lo = base + 9216;

        uint32_t a_hi[4][4], a_lo[4][4];
#pragma unroll
        for (int mf = 0; mf < 4; mf++) {
            int r0 = wm * 64 + mf * 16;
            ldsm4(a_hi[mf], as_hi + (r0 + a_row) * 24 + a_col);
            ldsm4(a_lo[mf], as_lo + (r0 + a_row) * 24 + a_col);
        }
        uint32_t b_hi[2][4], b_lo[2][4];
#pragma unroll
        for (int p = 0; p < 2; p++) {
            int c0 = wn * 32 + p * 16;
            ldsm4(b_hi[p], bs_hi + (c0 + b_row) * 24 + b_col);
            ldsm4(b_lo[p], bs_lo + (c0 + b_row) * 24 + b_col);
        }
#pragma unroll
        for (int nf = 0; nf < 4; nf++) {
            const uint32_t* bh = &b_hi[nf >> 1][(nf & 1) * 2];
            const uint32_t* bl = &b_lo[nf >> 1][(nf & 1) * 2];
#pragma unroll
            for (int mf = 0; mf < 4; mf++) {
                mma_bf16(acc[mf][nf], a_hi[mf], bh);
                mma_bf16(acc[mf][nf], a_hi[mf], bl);
                mma_bf16(acc[mf][nf], a_lo[mf], bh);
            }
        }
    }

#pragma unroll
    for (int mf = 0; mf < 4; mf++) {
        int r = m0 + wm * 64 + mf * 16 + group;
#pragma unroll
        for (int nf = 0; nf < 4; nf++) {
            int cc = n0 + wn * 32 + nf * 8 + tig * 2;
            float* dst = C0;
            int ccol = cc;
            if (cc >= ncut) { dst = C1; ccol = cc - ncut; }
            if (r < M)
                *(float2*)&dst[(size_t)r * ld + ccol] = make_float2(acc[mf][nf][0], acc[mf][nf][1]);
            if (r + 8 < M)
                *(float2*)&dst[(size_t)(r + 8) * ld + ccol] = make_float2(acc[mf][nf][2], acc[mf][nf][3]);
        }
    }
}

#define LRELU(v) ((v) > 0.f ? (v) : 0.2f * (v))

// ---------------- Layer 1 GAT + fused bf16 split of hidden -----------------
__global__ void gat1_kernel(const float* __restrict__ att1, const float* __restrict__ b1,
                            const float* __restrict__ lng, const float* __restrict__ lnb,
                            int Nn) {
    int i = blockIdx.x;
    int t = threadIdx.x;
    int h = t >> 5;
    int l = t & 31;
    int s = l >> 3;
    int c = l & 7;
    __shared__ float sout[256];
    __shared__ float red[4];
    __shared__ float red2[4];

    const float* xrp = g_xr1 + (size_t)i * L1C + h * 64 + c * 8;
    float4 xr0 = ((const float4*)xrp)[0];
    float4 xr1 = ((const float4*)xrp)[1];
    const float* atp = att1 + h * 64 + c * 8;
    float4 at0 = ((const float4*)atp)[0];
    float4 at1 = ((const float4*)atp)[1];

    float acc[8] = {0.f, 0.f, 0.f, 0.f, 0.f, 0.f, 0.f, 0.f};
    float den = 0.f;
    int e0 = g_off[i], deg = g_off[i + 1] - e0;
    for (int base = 0; base < deg; base += 4) {
        int valid = (base + s) < deg;
        int j = valid ? __ldg(&g_src[e0 + base + s]) : 0;
        const float4* px = (const float4*)(g_xl1 + (size_t)j * L1C + h * 64 + c * 8);
        float4 xa0 = px[0], xa1 = px[1];
        float term = LRELU(xa0.x + xr0.x) * at0.x + LRELU(xa0.y + xr0.y) * at0.y
                   + LRELU(xa0.z + xr0.z) * at0.z + LRELU(xa0.w + xr0.w) * at0.w
                   + LRELU(xa1.x + xr1.x) * at1.x + LRELU(xa1.y + xr1.y) * at1.y
                   + LRELU(xa1.z + xr1.z) * at1.z + LRELU(xa1.w + xr1.w) * at1.w;
        term += __shfl_xor_sync(0xffffffffu, term, 1);
        term += __shfl_xor_sync(0xffffffffu, term, 2);
        term += __shfl_xor_sync(0xffffffffu, term, 4);
        float a = valid ? __expf(term) : 0.f;
        acc[0] += a * xa0.x; acc[1] += a * xa0.y; acc[2] += a * xa0.z; acc[3] += a * xa0.w;
        acc[4] += a * xa1.x; acc[5] += a * xa1.y; acc[6] += a * xa1.z; acc[7] += a * xa1.w;
        den += a;
    }
#pragma unroll
    for (int k = 0; k < 8; k++) {
        acc[k] += __shfl_xor_sync(0xffffffffu, acc[k], 8);
        acc[k] += __shfl_xor_sync(0xffffffffu, acc[k], 16);
    }
    den += __shfl_xor_sync(0xffffffffu, den, 8);
    den += __shfl_xor_sync(0xffffffffu, den, 16);
    float inv = 1.f / (den + 1e-16f);
    if (s == 0) {
#pragma unroll
        for (int k = 0; k < 8; k++) sout[h * 64 + c * 8 + k] = acc[k] * inv;
    }
    __syncthreads();

    int w = t >> 5, lane = t & 31;
    float val = 0.f;
    if (t < 64)
        val = 0.25f * (sout[t] + sout[t + 64] + sout[t + 128] + sout[t + 192]) + b1[t];

    float v = (t < 64) ? val : 0.f;
#pragma unroll
    for (int o = 16; o; o >>= 1) v += __shfl_xor_sync(0xffffffffu, v, o);
    if (lane == 0) red[w] = v;
    __syncthreads();
    float mu = (red[0] + red[1] + red[2] + red[3]) * (1.f / 64.f);
    float dd = (t < 64) ? (val - mu) : 0.f;
    float v2 = dd * dd;
#pragma unroll
    for (int o = 16; o; o >>= 1) v2 += __shfl_xor_sync(0xffffffffu, v2, o);
    if (lane == 0) red2[w] = v2;
    __syncthreads();
    float var = (red2[0] + red2[1] + red2[2] + red2[3]) * (1.f / 64.f);
    if (t < 64) {
        float y = dd * rsqrtf(var + 1e-5f) * lng[t] + lnb[t];
        float hv = fmaxf(y, 0.f);
        g_h[(size_t)i * HID + t] = hv;
        __nv_bfloat16 hb = __float2bfloat16(hv);
        g_ahi[(size_t)i * HID + t] = hb;
        g_alo[(size_t)i * HID + t] = __float2bfloat16(hv - __bfloat162float(hb));
    }
}

// ---------------- Layer 2 GAT: warp per node, 4 edges/warp, LN fused -------
__global__ void gat2_kernel(const float* __restrict__ att2, const float* __restrict__ b2,
                            const float* __restrict__ lng, const float* __restrict__ lnb,
                            float* __restrict__ out, int Nn) {
    int w = threadIdx.x >> 5, l = threadIdx.x & 31;
    int i = blockIdx.x * 4 + w;
    if (i >= Nn) return;
    int s = l >> 3;
    int c = l & 7;
    const float* xl2 = g_xr1;
    const float* xr2 = g_xr1 + (size_t)NMAX * OUTD;

    const float* xrp = xr2 + (size_t)i * OUTD + c * 8;
    float4 xr0 = ((const float4*)xrp)[0];
    float4 xr1 = ((const float4*)xrp)[1];
    const float* atp = att2 + c * 8;
    float4 at0 = ((const float4*)atp)[0];
    float4 at1 = ((const float4*)atp)[1];

    float acc[8] = {0.f, 0.f, 0.f, 0.f, 0.f, 0.f, 0.f, 0.f};
    float den = 0.f;
    int e0 = g_off[i], deg = g_off[i + 1] - e0;
    for (int base = 0; base < deg; base += 4) {
        int valid = (base + s) < deg;
        int j = valid ? __ldg(&g_src[e0 + base + s]) : 0;
        const float4* px = (const float4*)(xl2 + (size_t)j * OUTD + c * 8);
        float4 xa0 = px[0], xa1 = px[1];
        float term = LRELU(xa0.x + xr0.x) * at0.x + LRELU(xa0.y + xr0.y) * at0.y
                   + LRELU(xa0.z + xr0.z) * at0.z + LRELU(xa0.w + xr0.w) * at0.w
                   + LRELU(xa1.x + xr1.x) * at1.x + LRELU(xa1.y + xr1.y) * at1.y
                   + LRELU(xa1.z + xr1.z) * at1.z + LRELU(xa1.w + xr1.w) * at1.w;
        term += __shfl_xor_sync(0xffffffffu, term, 1);
        term += __shfl_xor_sync(0xffffffffu, term, 2);
        term += __shfl_xor_sync(0xffffffffu, term, 4);
        float a = valid ? __expf(term) : 0.f;
        acc[0] += a * xa0.x; acc[1] += a * xa0.y; acc[2] += a * xa0.z; acc[3] += a * xa0.w;
        acc[4] += a * xa1.x; acc[5] += a * xa1.y; acc[6] += a * xa1.z; acc[7] += a * xa1.w;
        den += a;
    }
#pragma unroll
    for (int k = 0; k < 8; k++) {
        acc[k] += __shfl_xor_sync(0xffffffffu, acc[k], 8);
        acc[k] += __shfl_xor_sync(0xffffffffu, acc[k], 16);
    }
    den += __shfl_xor_sync(0xffffffffu, den, 8);
    den += __shfl_xor_sync(0xffffffffu, den, 16);
    float inv = 1.f / (den + 1e-16f);

    const float* bp = b2 + c * 8;
    float4 bb0 = ((const float4*)bp)[0];
    float4 bb1 = ((const float4*)bp)[1];
    float v[8];
    v[0] = acc[0] * inv + bb0.x; v[1] = acc[1] * inv + bb0.y;
    v[2] = acc[2] * inv + bb0.z; v[3] = acc[3] * inv + bb0.w;
    v[4] = acc[4] * inv + bb1.x; v[5] = acc[5] * inv + bb1.y;
    v[6] = acc[6] * inv + bb1.z; v[7] = acc[7] * inv + bb1.w;

    float sum = v[0] + v[1] + v[2] + v[3] + v[4] + v[5] + v[6] + v[7];
#pragma unroll
    for (int o = 16; o; o >>= 1) sum += __shfl_xor_sync(0xffffffffu, sum, o);
    float mu = sum * (1.f / 256.f);
    float q = 0.f;
    float d[8];
#pragma unroll
    for (int k = 0; k < 8; k++) { d[k] = v[k] - mu; q += d[k] * d[k]; }
#pragma unroll
    for (int o = 16; o; o >>= 1) q += __shfl_xor_sync(0xffffffffu, q, o);
    float var = q * (1.f / 256.f);
    float r = rsqrtf(var + 1e-5f);
    if (s == 0) {
        const float* gp = lng + c * 8;
        const float* np = lnb + c * 8;
        float4 gg0 = ((const float4*)gp)[0], gg1 = ((const float4*)gp)[1];
        float4 nn0 = ((const float4*)np)[0], nn1 = ((const float4*)np)[1];
        float4 o0, o1;
        o0.x = d[0] * r * gg0.x + nn0.x; o0.y = d[1] * r * gg0.y + nn0.y;
        o0.z = d[2] * r * gg0.z + nn0.z; o0.w = d[3] * r * gg0.w + nn0.w;
        o1.x = d[4] * r * gg1.x + nn1.x; o1.y = d[5] * r * gg1.y + nn1.y;
        o1.z = d[6] * r * gg1.z + nn1.z; o1.w = d[7] * r * gg1.w + nn1.w;
        float* op = out + (size_t)i * OUTD + c * 8;
        ((float4*)op)[0] = o0;
        ((float4*)op)[1] = o1;
    }
}

// ---------------- launch ----------------
extern "C" void kernel_launch(void* const* d_in, const int* in_sizes, int n_in,
                              void* d_out, int out_size) {
    const float* x    = (const float*)d_in[0];
    const int*   ei   = (const int*)d_in[1];
    const float* W1l  = (const float*)d_in[2];
    const float* W1r  = (const float*)d_in[3];
    const float* att1 = (const float*)d_in[4];
    const float* b1   = (const float*)d_in[5];
    const float* ln1g = (const float*)d_in[6];
    const float* ln1b = (const float*)d_in[7];
    const float* W2l  = (const float*)d_in[8];
    const float* W2r  = (const float*)d_in[9];
    const float* att2 = (const float*)d_in[10];
    const float* b2   = (const float*)d_in[11];
    const float* ln2g = (const float*)d_in[12];
    const float* ln2b = (const float*)d_in[13];
    float* out = (float*)d_out;

    int N = in_sizes[0] / IN_DIM;
    int E = in_sizes[1] / 2;
    if (N > NMAX) N = NMAX;
    if (E > EMAX) E = EMAX;
    int ETOT_RT = E + N;
    int nscan = (N + SCAN_BLK - 1) / SCAN_BLK;

    float *p_xl1, *p_xr1, *p_h;
    __nv_bfloat16 *p_ahi, *p_alo, *p_bhi, *p_blo, *p_bhi2, *p_blo2;
    cudaGetSymbolAddress((void**)&p_xl1, g_xl1);
    cudaGetSymbolAddress((void**)&p_xr1, g_xr1);
    cudaGetSymbolAddress((void**)&p_h,   g_h);
    cudaGetSymbolAddress((void**)&p_ahi, g_ahi);
    cudaGetSymbolAddress((void**)&p_alo, g_alo);
    cudaGetSymbolAddress((void**)&p_bhi, g_bhi);
    cudaGetSymbolAddress((void**)&p_blo, g_blo);
    cudaGetSymbolAddress((void**)&p_bhi2, g_bhi2);
    cudaGetSymbolAddress((void**)&p_blo2, g_blo2);
    float* p_xl2 = p_xr1;
    float* p_xr2 = p_xr1 + (size_t)NMAX * OUTD;

    cudaFuncSetAttribute(gemm1_ares_kernel, cudaFuncAttributeMaxDynamicSharedMemorySize, G1_SMEM_BYTES);
    cudaFuncSetAttribute(mma_gemm_kernel<4>, cudaFuncAttributeMaxDynamicSharedMemorySize, GEMM_SMEM_BYTES);

    static cudaStream_t s2 = nullptr;
    static cudaEvent_t ev_fork = nullptr, ev_g1 = nullptr;
    if (!s2) {
        cudaStreamCreateWithFlags(&s2, cudaStreamNonBlocking);
        cudaEventCreateWithFlags(&ev_fork, cudaEventDisableTiming);
        cudaEventCreateWithFlags(&ev_g1, cudaEventDisableTiming);
    }

    cudaEventRecord(ev_fork, 0);
    cudaStreamWaitEvent(s2, ev_fork, 0);

    // ---- stream s2: layer-1 GEMM chain (A-resident) ----
    {
        int n4 = N * IN_DIM / 4;
        conv_split_kernel<<<(n4 + 255) / 256, 256, 0, s2>>>(x, p_ahi, p_alo, n4);
        pack_bt_kernel<<<(512 * 256 + 255) / 256, 256, 0, s2>>>(W1l, W1r, p_bhi, p_blo, 256, 256);
        pack_bt_kernel<<<(128 * 64 + 255) / 256, 256, 0, s2>>>(W2l, W2r, p_bhi2, p_blo2, 64, 64);
        gemm1_ares_kernel<<<(N + 127) / 128, 256, G1_SMEM_BYTES, s2>>>(
            p_ahi, p_alo, p_bhi, p_blo, p_xl1, p_xr1, N);
        cudaEventRecord(ev_g1, s2);
    }

    // ---- default stream: CSR build (concurrent) ----
    zero_deg_kernel<<<(N + 256) / 256, 256>>>(N);
    hist_kernel<<<(ETOT_RT + 255) / 256, 256>>>(ei, E, N);
    scan1_kernel<<<nscan, SCAN_BLK>>>(N);
    scan2_kernel<<<1, 64>>>(nscan, N);
    scan3_kernel<<<nscan, SCAN_BLK>>>(N);
    scatter_kernel<<<(ETOT_RT + 255) / 256, 256>>>(ei, E, N);

    cudaStreamWaitEvent(0, ev_g1, 0);

    gat1_kernel<<<N, 128>>>(att1, b1, ln1g, ln1b, N);

    {
        dim3 grid(1, (N + 127) / 128);
        mma_gemm_kernel<4><<<grid, 256, GEMM_SMEM_BYTES>>>(p_ahi, p_alo, p_bhi2, p_blo2,
                                                           p_xl2, p_xr2, N, 64, 64);
    }

    gat2_kernel<<<(N + 3) / 4, 128>>>(att2, b2, ln2g, ln2b, out, N);
}

// round 12
// speedup vs baseline: 1.3524x; 1.3524x over previous
#include <cuda_runtime.h>
#include <cuda_bf16.h>
#include <cuda_fp16.h>
#include <math.h>
#include <stdint.h>

#define NMAX 50000
#define EMAX 800000
#define ETOTAL (EMAX + NMAX)
#define IN_DIM 256
#define HID 64
#define L1C 256
#define OUTD 64
#define SCAN_BLK 1024
#define NSCAN ((NMAX + SCAN_BLK - 1) / SCAN_BLK)

// fp16 GEMM: 3 stages x 2 arrays x [128][24] half
#define HG_STAGE_ELEMS (2 * 128 * 24)
#define HG_SMEM_BYTES (3 * HG_STAGE_ELEMS * 2)

// ---------------- scratch (device globals; allocation-free) ----------------
__device__ float g_xl1[(size_t)NMAX * L1C];
__device__ float g_xr1[(size_t)NMAX * L1C];   // reused for layer2 xl2/xr2
__device__ float g_h[(size_t)NMAX * HID];
__device__ __half g_ah[(size_t)NMAX * 256];   // fp16 A (x, then h)
__device__ __half g_bh[512 * 256];            // packed W1 transposed fp16
__device__ __half g_bh2[128 * 64];            // packed W2 transposed fp16
__device__ int   g_deg[NMAX + 1];
__device__ int   g_off[NMAX + 1];
__device__ int   g_cur[NMAX];
__device__ int   g_src[ETOTAL];
__device__ int   g_bsum[NSCAN + 1];

// ---------------- CSR build ----------------
__global__ void zero_deg_kernel(int n) {
    int i = blockIdx.x * blockDim.x + threadIdx.x;
    if (i <= n) g_deg[i] = 0;
}

__global__ void hist_kernel(const int* __restrict__ ei, int E, int n) {
    int e = blockIdx.x * blockDim.x + threadIdx.x;
    int tot = E + n;
    if (e < tot) {
        int d = (e < E) ? ei[E + e] : (e - E);
        if (d < 0) d = 0;
        if (d >= n) d = n - 1;
        atomicAdd(&g_deg[d], 1);
    }
}

__global__ void scan1_kernel(int n) {
    __shared__ int sh[SCAN_BLK];
    int tid = threadIdx.x;
    int idx = blockIdx.x * SCAN_BLK + tid;
    int v = (idx < n) ? g_deg[idx] : 0;
    sh[tid] = v;
    __syncthreads();
    for (int d = 1; d < SCAN_BLK; d <<= 1) {
        int t = sh[tid];
        int add = (tid >= d) ? sh[tid - d] : 0;
        __syncthreads();
        sh[tid] = t + add;
        __syncthreads();
    }
    if (idx < n) g_off[idx] = sh[tid] - v;
    if (tid == SCAN_BLK - 1) g_bsum[blockIdx.x] = sh[tid];
}

__global__ void scan2_kernel(int nb, int n) {
    __shared__ int wsum[2];
    int t = threadIdx.x;
    int w = t >> 5, l = t & 31;
    int v = (t < nb) ? g_bsum[t] : 0;
    int sc = v;
#pragma unroll
    for (int d = 1; d < 32; d <<= 1) {
        int u = __shfl_up_sync(0xffffffffu, sc, d);
        if (l >= d) sc += u;
    }
    if (l == 31) wsum[w] = sc;
    __syncthreads();
    int base = (w == 1) ? wsum[0] : 0;
    if (t < nb) g_bsum[t] = sc - v + base;
    if (t == 0) {
        int tot = wsum[0] + ((nb > 32) ? wsum[1] : 0);
        if (nb <= 32) tot = wsum[0];
        g_off[n] = tot;
    }
}

__global__ void scan3_kernel(int n) {
    int idx = blockIdx.x * SCAN_BLK + threadIdx.x;
    if (idx < n) {
        int o = g_off[idx] + g_bsum[blockIdx.x];
        g_off[idx] = o;
        g_cur[idx] = o;
    }
}

__global__ void scatter_kernel(const int* __restrict__ ei, int E, int n) {
    int e = blockIdx.x * blockDim.x + threadIdx.x;
    int tot = E + n;
    if (e < tot) {
        int s, d;
        if (e < E) { s = ei[e]; d = ei[E + e]; }
        else       { s = d = e - E; }
        if (s < 0) s = 0; if (s >= n) s = n - 1;
        if (d < 0) d = 0; if (d >= n) d = n - 1;
        int pos = atomicAdd(&g_cur[d], 1);
        if (pos >= 0 && pos < ETOTAL) g_src[pos] = s;
    }
}

// ---------------- fp32 -> fp16 convert ----------------
__global__ void conv_h_kernel(const float* __restrict__ in, __half* __restrict__ out, int n4) {
    int i = blockIdx.x * blockDim.x + threadIdx.x;
    if (i < n4) {
        float4 v = ((const float4*)in)[i];
        __half2 h0 = __floats2half2_rn(v.x, v.y);
        __half2 h1 = __floats2half2_rn(v.z, v.w);
        ((__half2*)out)[2 * i] = h0;
        ((__half2*)out)[2 * i + 1] = h1;
    }
}

// ---------------- pack Wl|Wr -> Bt[n][k] (transposed), fp16 ----------
__global__ void pack_bt_h_kernel(const float* __restrict__ Wl, const float* __restrict__ Wr,
                                 __half* __restrict__ bh, int K, int Nhalf) {
    int idx = blockIdx.x * blockDim.x + threadIdx.x;
    int tot = 2 * Nhalf * K;
    if (idx < tot) {
        int n = idx / K, k = idx % K;
        float v = (n < Nhalf) ? Wl[(size_t)k * Nhalf + n] : Wr[(size_t)k * Nhalf + (n - Nhalf)];
        bh[idx] = __float2half_rn(v);
    }
}

// ---------------- async copy + ldmatrix + mma helpers ----------------
__device__ __forceinline__ void cp16(void* sdst, const void* gsrc, int src_bytes) {
    uint32_t s = (uint32_t)__cvta_generic_to_shared(sdst);
    asm volatile("cp.async.cg.shared.global [%0], [%1], 16, %2;\n"
                 :: "r"(s), "l"(gsrc), "r"(src_bytes));
}
__device__ __forceinline__ void cp_commit() { asm volatile("cp.async.commit_group;\n"); }
__device__ __forceinline__ void cp_wait1() { asm volatile("cp.async.wait_group 1;\n"); }
__device__ __forceinline__ void cp_wait0() { asm volatile("cp.async.wait_group 0;\n"); }

__device__ __forceinline__ void ldsm4(uint32_t r[4], const void* p) {
    uint32_t a = (uint32_t)__cvta_generic_to_shared(p);
    asm volatile("ldmatrix.sync.aligned.m8n8.x4.shared.b16 {%0,%1,%2,%3}, [%4];\n"
                 : "=r"(r[0]), "=r"(r[1]), "=r"(r[2]), "=r"(r[3]) : "r"(a));
}

__device__ __forceinline__ void mma_f16(float d[4], const uint32_t a[4], const uint32_t b[2]) {
    asm volatile(
        "mma.sync.aligned.m16n8k16.row.col.f32.f16.f16.f32 "
        "{%0,%1,%2,%3}, {%4,%5,%6,%7}, {%8,%9}, {%0,%1,%2,%3};\n"
        : "+f"(d[0]), "+f"(d[1]), "+f"(d[2]), "+f"(d[3])
        : "r"(a[0]), "r"(a[1]), "r"(a[2]), "r"(a[3]), "r"(b[0]), "r"(b[1]));
}

// ---- fp16 tensor-core GEMM, single term, 3-stage cp.async, ldmatrix ----
// C[M, Ntot] = A[M,K] x Bt[Ntot,K]^T; block 128x128, 8 warps (64x32 warp tiles).
template <int KCHUNKS>
__global__ __launch_bounds__(256, 2)
void hgemm_kernel(const __half* __restrict__ A, const __half* __restrict__ Bt,
                  float* __restrict__ C0, float* __restrict__ C1,
                  int M, int ncut, int ld) {
    constexpr int K = KCHUNKS * 16;
    extern __shared__ __half sm[];
    __half* stage_base[3] = { sm, sm + HG_STAGE_ELEMS, sm + 2 * HG_STAGE_ELEMS };

    int t = threadIdx.x;
    int lane = t & 31, wid = t >> 5;
    int wm = wid & 1, wn = wid >> 1;          // 2 x 4 warp grid
    int group = lane >> 2, tig = lane & 3;
    int m0 = blockIdx.y * 128, n0 = blockIdx.x * 128;

    int a_row = lane & 15;
    int a_col = ((lane >> 4) & 1) * 8;
    int b_row = ((lane >> 4) & 1) * 8 + (lane & 7);
    int b_col = ((lane >> 3) & 1) * 8;

    float acc[4][4][4];
#pragma unroll
    for (int i = 0; i < 4; i++)
#pragma unroll
        for (int j = 0; j < 4; j++)
#pragma unroll
            for (int q = 0; q < 4; q++) acc[i][j][q] = 0.f;

    int lrow = t >> 1, lkq = (t & 1) * 8;
    int grow = m0 + lrow;
    int abytes = (grow < M) ? 16 : 0;
    const __half* pA = A + (size_t)(grow < M ? grow : 0) * K + lkq;
    const __half* pB = Bt + (size_t)(n0 + lrow) * K + lkq;
    int lofs = lrow * 24 + lkq;

    auto load_stage = [&](int c, int st) {
        __half* base = stage_base[st];
        int ko = c * 16;
        cp16(base + lofs,        pA + ko, abytes);
        cp16(base + 3072 + lofs, pB + ko, 16);
        cp_commit();
    };

    load_stage(0, 0);
    if (KCHUNKS > 1) load_stage(1, 1);

#pragma unroll
    for (int c = 0; c < KCHUNKS; c++) {
        if (c + 1 < KCHUNKS) cp_wait1(); else cp_wait0();
        __syncthreads();
        if (c + 2 < KCHUNKS) load_stage(c + 2, (c + 2) % 3);

        __half* base = stage_base[c % 3];
        __half* as = base;
        __half* bs = base + 3072;

        uint32_t af[4][4];
#pragma unroll
        for (int mf = 0; mf < 4; mf++) {
            int r0 = wm * 64 + mf * 16;
            ldsm4(af[mf], as + (r0 + a_row) * 24 + a_col);
        }
        uint32_t bf[2][4];
#pragma unroll
        for (int p = 0; p < 2; p++) {
            int c0 = wn * 32 + p * 16;
            ldsm4(bf[p], bs + (c0 + b_row) * 24 + b_col);
        }
#pragma unroll
        for (int nf = 0; nf < 4; nf++) {
            const uint32_t* bp = &bf[nf >> 1][(nf & 1) * 2];
#pragma unroll
            for (int mf = 0; mf < 4; mf++)
                mma_f16(acc[mf][nf], af[mf], bp);
        }
    }

#pragma unroll
    for (int mf = 0; mf < 4; mf++) {
        int r = m0 + wm * 64 + mf * 16 + group;
#pragma unroll
        for (int nf = 0; nf < 4; nf++) {
            int cc = n0 + wn * 32 + nf * 8 + tig * 2;
            float* dst = C0;
            int ccol = cc;
            if (cc >= ncut) { dst = C1; ccol = cc - ncut; }
            if (r < M)
                *(float2*)&dst[(size_t)r * ld + ccol] = make_float2(acc[mf][nf][0], acc[mf][nf][1]);
            if (r + 8 < M)
                *(float2*)&dst[(size_t)(r + 8) * ld + ccol] = make_float2(acc[mf][nf][2], acc[mf][nf][3]);
        }
    }
}

#define LRELU(v) ((v) > 0.f ? (v) : 0.2f * (v))

// ---------------- Layer 1 GAT + fused fp16 convert of hidden ---------------
__global__ void gat1_kernel(const float* __restrict__ att1, const float* __restrict__ b1,
                            const float* __restrict__ lng, const float* __restrict__ lnb,
                            int Nn) {
    int i = blockIdx.x;
    int t = threadIdx.x;
    int h = t >> 5;
    int l = t & 31;
    int s = l >> 3;
    int c = l & 7;
    __shared__ float sout[256];
    __shared__ float red[4];
    __shared__ float red2[4];

    const float* xrp = g_xr1 + (size_t)i * L1C + h * 64 + c * 8;
    float4 xr0 = ((const float4*)xrp)[0];
    float4 xr1 = ((const float4*)xrp)[1];
    const float* atp = att1 + h * 64 + c * 8;
    float4 at0 = ((const float4*)atp)[0];
    float4 at1 = ((const float4*)atp)[1];

    float acc[8] = {0.f, 0.f, 0.f, 0.f, 0.f, 0.f, 0.f, 0.f};
    float den = 0.f;
    int e0 = g_off[i], deg = g_off[i + 1] - e0;
    for (int base = 0; base < deg; base += 4) {
        int valid = (base + s) < deg;
        int j = valid ? __ldg(&g_src[e0 + base + s]) : 0;
        const float4* px = (const float4*)(g_xl1 + (size_t)j * L1C + h * 64 + c * 8);
        float4 xa0 = px[0], xa1 = px[1];
        float term = LRELU(xa0.x + xr0.x) * at0.x + LRELU(xa0.y + xr0.y) * at0.y
                   + LRELU(xa0.z + xr0.z) * at0.z + LRELU(xa0.w + xr0.w) * at0.w
                   + LRELU(xa1.x + xr1.x) * at1.x + LRELU(xa1.y + xr1.y) * at1.y
                   + LRELU(xa1.z + xr1.z) * at1.z + LRELU(xa1.w + xr1.w) * at1.w;
        term += __shfl_xor_sync(0xffffffffu, term, 1);
        term += __shfl_xor_sync(0xffffffffu, term, 2);
        term += __shfl_xor_sync(0xffffffffu, term, 4);
        float a = valid ? __expf(term) : 0.f;
        acc[0] += a * xa0.x; acc[1] += a * xa0.y; acc[2] += a * xa0.z; acc[3] += a * xa0.w;
        acc[4] += a * xa1.x; acc[5] += a * xa1.y; acc[6] += a * xa1.z; acc[7] += a * xa1.w;
        den += a;
    }
#pragma unroll
    for (int k = 0; k < 8; k++) {
        acc[k] += __shfl_xor_sync(0xffffffffu, acc[k], 8);
        acc[k] += __shfl_xor_sync(0xffffffffu, acc[k], 16);
    }
    den += __shfl_xor_sync(0xffffffffu, den, 8);
    den += __shfl_xor_sync(0xffffffffu, den, 16);
    float inv = 1.f / (den + 1e-16f);
    if (s == 0) {
#pragma unroll
        for (int k = 0; k < 8; k++) sout[h * 64 + c * 8 + k] = acc[k] * inv;
    }
    __syncthreads();

    int w = t >> 5, lane = t & 31;
    float val = 0.f;
    if (t < 64)
        val = 0.25f * (sout[t] + sout[t + 64] + sout[t + 128] + sout[t + 192]) + b1[t];

    float v = (t < 64) ? val : 0.f;
#pragma unroll
    for (int o = 16; o; o >>= 1) v += __shfl_xor_sync(0xffffffffu, v, o);
    if (lane == 0) red[w] = v;
    __syncthreads();
    float mu = (red[0] + red[1] + red[2] + red[3]) * (1.f / 64.f);
    float dd = (t < 64) ? (val - mu) : 0.f;
    float v2 = dd * dd;
#pragma unroll
    for (int o = 16; o; o >>= 1) v2 += __shfl_xor_sync(0xffffffffu, v2, o);
    if (lane == 0) red2[w] = v2;
    __syncthreads();
    float var = (red2[0] + red2[1] + red2[2] + red2[3]) * (1.f / 64.f);
    if (t < 64) {
        float y = dd * rsqrtf(var + 1e-5f) * lng[t] + lnb[t];
        float hv = fmaxf(y, 0.f);
        g_h[(size_t)i * HID + t] = hv;
        g_ah[(size_t)i * HID + t] = __float2half_rn(hv);
    }
}

// ---------------- Layer 2 GAT: warp per node, 4 edges/warp, LN fused -------
__global__ void gat2_kernel(const float* __restrict__ att2, const float* __restrict__ b2,
                            const float* __restrict__ lng, const float* __restrict__ lnb,
                            float* __restrict__ out, int Nn) {
    int w = threadIdx.x >> 5, l = threadIdx.x & 31;
    int i = blockIdx.x * 4 + w;
    if (i >= Nn) return;
    int s = l >> 3;
    int c = l & 7;
    const float* xl2 = g_xr1;
    const float* xr2 = g_xr1 + (size_t)NMAX * OUTD;

    const float* xrp = xr2 + (size_t)i * OUTD + c * 8;
    float4 xr0 = ((const float4*)xrp)[0];
    float4 xr1 = ((const float4*)xrp)[1];
    const float* atp = att2 + c * 8;
    float4 at0 = ((const float4*)atp)[0];
    float4 at1 = ((const float4*)atp)[1];

    float acc[8] = {0.f, 0.f, 0.f, 0.f, 0.f, 0.f, 0.f, 0.f};
    float den = 0.f;
    int e0 = g_off[i], deg = g_off[i + 1] - e0;
    for (int base = 0; base < deg; base += 4) {
        int valid = (base + s) < deg;
        int j = valid ? __ldg(&g_src[e0 + base + s]) : 0;
        const float4* px = (const float4*)(xl2 + (size_t)j * OUTD + c * 8);
        float4 xa0 = px[0], xa1 = px[1];
        float term = LRELU(xa0.x + xr0.x) * at0.x + LRELU(xa0.y + xr0.y) * at0.y
                   + LRELU(xa0.z + xr0.z) * at0.z + LRELU(xa0.w + xr0.w) * at0.w
                   + LRELU(xa1.x + xr1.x) * at1.x + LRELU(xa1.y + xr1.y) * at1.y
                   + LRELU(xa1.z + xr1.z) * at1.z + LRELU(xa1.w + xr1.w) * at1.w;
        term += __shfl_xor_sync(0xffffffffu, term, 1);
        term += __shfl_xor_sync(0xffffffffu, term, 2);
        term += __shfl_xor_sync(0xffffffffu, term, 4);
        float a = valid ? __expf(term) : 0.f;
        acc[0] += a * xa0.x; acc[1] += a * xa0.y; acc[2] += a * xa0.z; acc[3] += a * xa0.w;
        acc[4] += a * xa1.x; acc[5] += a * xa1.y; acc[6] += a * xa1.z; acc[7] += a * xa1.w;
        den += a;
    }
#pragma unroll
    for (int k = 0; k < 8; k++) {
        acc[k] += __shfl_xor_sync(0xffffffffu, acc[k], 8);
        acc[k] += __shfl_xor_sync(0xffffffffu, acc[k], 16);
    }
    den += __shfl_xor_sync(0xffffffffu, den, 8);
    den += __shfl_xor_sync(0xffffffffu, den, 16);
    float inv = 1.f / (den + 1e-16f);

    const float* bp = b2 + c * 8;
    float4 bb0 = ((const float4*)bp)[0];
    float4 bb1 = ((const float4*)bp)[1];
    float v[8];
    v[0] = acc[0] * inv + bb0.x; v[1] = acc[1] * inv + bb0.y;
    v[2] = acc[2] * inv + bb0.z; v[3] = acc[3] * inv + bb0.w;
    v[4] = acc[4] * inv + bb1.x; v[5] = acc[5] * inv + bb1.y;
    v[6] = acc[6] * inv + bb1.z; v[7] = acc[7] * inv + bb1.w;

    float sum = v[0] + v[1] + v[2] + v[3] + v[4] + v[5] + v[6] + v[7];
#pragma unroll
    for (int o = 16; o; o >>= 1) sum += __shfl_xor_sync(0xffffffffu, sum, o);
    float mu = sum * (1.f / 256.f);
    float q = 0.f;
    float d[8];
#pragma unroll
    for (int k = 0; k < 8; k++) { d[k] = v[k] - mu; q += d[k] * d[k]; }
#pragma unroll
    for (int o = 16; o; o >>= 1) q += __shfl_xor_sync(0xffffffffu, q, o);
    float var = q * (1.f / 256.f);
    float r = rsqrtf(var + 1e-5f);
    if (s == 0) {
        const float* gp = lng + c * 8;
        const float* np = lnb + c * 8;
        float4 gg0 = ((const float4*)gp)[0], gg1 = ((const float4*)gp)[1];
        float4 nn0 = ((const float4*)np)[0], nn1 = ((const float4*)np)[1];
        float4 o0, o1;
        o0.x = d[0] * r * gg0.x + nn0.x; o0.y = d[1] * r * gg0.y + nn0.y;
        o0.z = d[2] * r * gg0.z + nn0.z; o0.w = d[3] * r * gg0.w + nn0.w;
        o1.x = d[4] * r * gg1.x + nn1.x; o1.y = d[5] * r * gg1.y + nn1.y;
        o1.z = d[6] * r * gg1.z + nn1.z; o1.w = d[7] * r * gg1.w + nn1.w;
        float* op = out + (size_t)i * OUTD + c * 8;
        ((float4*)op)[0] = o0;
        ((float4*)op)[1] = o1;
    }
}

// ---------------- launch ----------------
extern "C" void kernel_launch(void* const* d_in, const int* in_sizes, int n_in,
                              void* d_out, int out_size) {
    const float* x    = (const float*)d_in[0];
    const int*   ei   = (const int*)d_in[1];
    const float* W1l  = (const float*)d_in[2];
    const float* W1r  = (const float*)d_in[3];
    const float* att1 = (const float*)d_in[4];
    const float* b1   = (const float*)d_in[5];
    const float* ln1g = (const float*)d_in[6];
    const float* ln1b = (const float*)d_in[7];
    const float* W2l  = (const float*)d_in[8];
    const float* W2r  = (const float*)d_in[9];
    const float* att2 = (const float*)d_in[10];
    const float* b2   = (const float*)d_in[11];
    const float* ln2g = (const float*)d_in[12];
    const float* ln2b = (const float*)d_in[13];
    float* out = (float*)d_out;

    int N = in_sizes[0] / IN_DIM;
    int E = in_sizes[1] / 2;
    if (N > NMAX) N = NMAX;
    if (E > EMAX) E = EMAX;
    int ETOT_RT = E + N;
    int nscan = (N + SCAN_BLK - 1) / SCAN_BLK;

    float *p_xl1, *p_xr1, *p_h;
    __half *p_ah, *p_bh, *p_bh2;
    cudaGetSymbolAddress((void**)&p_xl1, g_xl1);
    cudaGetSymbolAddress((void**)&p_xr1, g_xr1);
    cudaGetSymbolAddress((void**)&p_h,   g_h);
    cudaGetSymbolAddress((void**)&p_ah,  g_ah);
    cudaGetSymbolAddress((void**)&p_bh,  g_bh);
    cudaGetSymbolAddress((void**)&p_bh2, g_bh2);
    float* p_xl2 = p_xr1;
    float* p_xr2 = p_xr1 + (size_t)NMAX * OUTD;

    cudaFuncSetAttribute(hgemm_kernel<16>, cudaFuncAttributeMaxDynamicSharedMemorySize, HG_SMEM_BYTES);
    cudaFuncSetAttribute(hgemm_kernel<4>,  cudaFuncAttributeMaxDynamicSharedMemorySize, HG_SMEM_BYTES);

    static cudaStream_t s2 = nullptr;
    static cudaEvent_t ev_fork = nullptr, ev_g1 = nullptr;
    if (!s2) {
        cudaStreamCreateWithFlags(&s2, cudaStreamNonBlocking);
        cudaEventCreateWithFlags(&ev_fork, cudaEventDisableTiming);
        cudaEventCreateWithFlags(&ev_g1, cudaEventDisableTiming);
    }

    cudaEventRecord(ev_fork, 0);
    cudaStreamWaitEvent(s2, ev_fork, 0);

    // ---- stream s2: layer-1 GEMM chain (fp16 single-term) ----
    {
        int n4 = N * IN_DIM / 4;
        conv_h_kernel<<<(n4 + 255) / 256, 256, 0, s2>>>(x, p_ah, n4);
        pack_bt_h_kernel<<<(512 * 256 + 255) / 256, 256, 0, s2>>>(W1l, W1r, p_bh, 256, 256);
        pack_bt_h_kernel<<<(128 * 64 + 255) / 256, 256, 0, s2>>>(W2l, W2r, p_bh2, 64, 64);
        dim3 grid(4, (N + 127) / 128);
        hgemm_kernel<16><<<grid, 256, HG_SMEM_BYTES, s2>>>(p_ah, p_bh, p_xl1, p_xr1, N, 256, 256);
        cudaEventRecord(ev_g1, s2);
    }

    // ---- default stream: CSR build (concurrent) ----
    zero_deg_kernel<<<(N + 256) / 256, 256>>>(N);
    hist_kernel<<<(ETOT_RT + 255) / 256, 256>>>(ei, E, N);
    scan1_kernel<<<nscan, SCAN_BLK>>>(N);
    scan2_kernel<<<1, 64>>>(nscan, N);
    scan3_kernel<<<nscan, SCAN_BLK>>>(N);
    scatter_kernel<<<(ETOT_RT + 255) / 256, 256>>>(ei, E, N);

    cudaStreamWaitEvent(0, ev_g1, 0);

    gat1_kernel<<<N, 128>>>(att1, b1, ln1g, ln1b, N);

    {
        dim3 grid(1, (N + 127) / 128);
        hgemm_kernel<4><<<grid, 256, HG_SMEM_BYTES>>>(p_ah, p_bh2, p_xl2, p_xr2, N, 64, 64);
    }

    gat2_kernel<<<(N + 3) / 4, 128>>>(att2, b2, ln2g, ln2b, out, N);
}

// round 13
// speedup vs baseline: 1.4439x; 1.0676x over previous
#include <cuda_runtime.h>
#include <cuda_bf16.h>
#include <cuda_fp16.h>
#include <math.h>
#include <stdint.h>

#define NMAX 50000
#define EMAX 800000
#define ETOTAL (EMAX + NMAX)
#define IN_DIM 256
#define HID 64
#define L1C 256
#define OUTD 64
#define SCAN_BLK 1024
#define NSCAN ((NMAX + SCAN_BLK - 1) / SCAN_BLK)

// fp16 GEMM: 3 stages x 2 arrays x [128][24] half
#define HG_STAGE_ELEMS (2 * 128 * 24)
#define HG_SMEM_BYTES (3 * HG_STAGE_ELEMS * 2)

// ---------------- scratch (device globals; allocation-free) ----------------
__device__ float  g_xr1[(size_t)NMAX * L1C];  // layer1 xr fp32; reused for layer2 xr2
__device__ __half g_xlh[(size_t)NMAX * 256];  // layer1 xl fp16 (ld 256); layer2 xl2 (ld 64)
__device__ float  g_h[(size_t)NMAX * HID];
__device__ __half g_ah[(size_t)NMAX * 256];   // fp16 A (x, then h)
__device__ __half g_bh[512 * 256];            // packed W1 transposed fp16
__device__ __half g_bh2[128 * 64];            // packed W2 transposed fp16
__device__ int   g_deg[NMAX + 1];
__device__ int   g_off[NMAX + 1];
__device__ int   g_cur[NMAX];
__device__ int   g_src[ETOTAL];
__device__ int   g_bsum[NSCAN + 1];

// ---------------- CSR build ----------------
__global__ void zero_deg_kernel(int n) {
    int i = blockIdx.x * blockDim.x + threadIdx.x;
    if (i <= n) g_deg[i] = 0;
}

__global__ void hist_kernel(const int* __restrict__ ei, int E, int n) {
    int e = blockIdx.x * blockDim.x + threadIdx.x;
    int tot = E + n;
    if (e < tot) {
        int d = (e < E) ? ei[E + e] : (e - E);
        if (d < 0) d = 0;
        if (d >= n) d = n - 1;
        atomicAdd(&g_deg[d], 1);
    }
}

__global__ void scan1_kernel(int n) {
    __shared__ int sh[SCAN_BLK];
    int tid = threadIdx.x;
    int idx = blockIdx.x * SCAN_BLK + tid;
    int v = (idx < n) ? g_deg[idx] : 0;
    sh[tid] = v;
    __syncthreads();
    for (int d = 1; d < SCAN_BLK; d <<= 1) {
        int t = sh[tid];
        int add = (tid >= d) ? sh[tid - d] : 0;
        __syncthreads();
        sh[tid] = t + add;
        __syncthreads();
    }
    if (idx < n) g_off[idx] = sh[tid] - v;
    if (tid == SCAN_BLK - 1) g_bsum[blockIdx.x] = sh[tid];
}

__global__ void scan2_kernel(int nb, int n) {
    __shared__ int wsum[2];
    int t = threadIdx.x;
    int w = t >> 5, l = t & 31;
    int v = (t < nb) ? g_bsum[t] : 0;
    int sc = v;
#pragma unroll
    for (int d = 1; d < 32; d <<= 1) {
        int u = __shfl_up_sync(0xffffffffu, sc, d);
        if (l >= d) sc += u;
    }
    if (l == 31) wsum[w] = sc;
    __syncthreads();
    int base = (w == 1) ? wsum[0] : 0;
    if (t < nb) g_bsum[t] = sc - v + base;
    if (t == 0) {
        int tot = wsum[0] + ((nb > 32) ? wsum[1] : 0);
        if (nb <= 32) tot = wsum[0];
        g_off[n] = tot;
    }
}

__global__ void scan3_kernel(int n) {
    int idx = blockIdx.x * SCAN_BLK + threadIdx.x;
    if (idx < n) {
        int o = g_off[idx] + g_bsum[blockIdx.x];
        g_off[idx] = o;
        g_cur[idx] = o;
    }
}

__global__ void scatter_kernel(const int* __restrict__ ei, int E, int n) {
    int e = blockIdx.x * blockDim.x + threadIdx.x;
    int tot = E + n;
    if (e < tot) {
        int s, d;
        if (e < E) { s = ei[e]; d = ei[E + e]; }
        else       { s = d = e - E; }
        if (s < 0) s = 0; if (s >= n) s = n - 1;
        if (d < 0) d = 0; if (d >= n) d = n - 1;
        int pos = atomicAdd(&g_cur[d], 1);
        if (pos >= 0 && pos < ETOTAL) g_src[pos] = s;
    }
}

// ---------------- fp32 -> fp16 convert ----------------
__global__ void conv_h_kernel(const float* __restrict__ in, __half* __restrict__ out, int n4) {
    int i = blockIdx.x * blockDim.x + threadIdx.x;
    if (i < n4) {
        float4 v = ((const float4*)in)[i];
        __half2 h0 = __floats2half2_rn(v.x, v.y);
        __half2 h1 = __floats2half2_rn(v.z, v.w);
        ((__half2*)out)[2 * i] = h0;
        ((__half2*)out)[2 * i + 1] = h1;
    }
}

// ---------------- pack Wl|Wr -> Bt[n][k] (transposed), fp16 ----------
__global__ void pack_bt_h_kernel(const float* __restrict__ Wl, const float* __restrict__ Wr,
                                 __half* __restrict__ bh, int K, int Nhalf) {
    int idx = blockIdx.x * blockDim.x + threadIdx.x;
    int tot = 2 * Nhalf * K;
    if (idx < tot) {
        int n = idx / K, k = idx % K;
        float v = (n < Nhalf) ? Wl[(size_t)k * Nhalf + n] : Wr[(size_t)k * Nhalf + (n - Nhalf)];
        bh[idx] = __float2half_rn(v);
    }
}

// ---------------- async copy + ldmatrix + mma helpers ----------------
__device__ __forceinline__ void cp16(void* sdst, const void* gsrc, int src_bytes) {
    uint32_t s = (uint32_t)__cvta_generic_to_shared(sdst);
    asm volatile("cp.async.cg.shared.global [%0], [%1], 16, %2;\n"
                 :: "r"(s), "l"(gsrc), "r"(src_bytes));
}
__device__ __forceinline__ void cp_commit() { asm volatile("cp.async.commit_group;\n"); }
__device__ __forceinline__ void cp_wait1() { asm volatile("cp.async.wait_group 1;\n"); }
__device__ __forceinline__ void cp_wait0() { asm volatile("cp.async.wait_group 0;\n"); }

__device__ __forceinline__ void ldsm4(uint32_t r[4], const void* p) {
    uint32_t a = (uint32_t)__cvta_generic_to_shared(p);
    asm volatile("ldmatrix.sync.aligned.m8n8.x4.shared.b16 {%0,%1,%2,%3}, [%4];\n"
                 : "=r"(r[0]), "=r"(r[1]), "=r"(r[2]), "=r"(r[3]) : "r"(a));
}

__device__ __forceinline__ void mma_f16(float d[4], const uint32_t a[4], const uint32_t b[2]) {
    asm volatile(
        "mma.sync.aligned.m16n8k16.row.col.f32.f16.f16.f32 "
        "{%0,%1,%2,%3}, {%4,%5,%6,%7}, {%8,%9}, {%0,%1,%2,%3};\n"
        : "+f"(d[0]), "+f"(d[1]), "+f"(d[2]), "+f"(d[3])
        : "r"(a[0]), "r"(a[1]), "r"(a[2]), "r"(a[3]), "r"(b[0]), "r"(b[1]));
}

// ---- fp16 tensor-core GEMM; cols < ncut -> H0 (fp16), else C1 (fp32) ----
template <int KCHUNKS>
__global__ __launch_bounds__(256, 2)
void hgemm_kernel(const __half* __restrict__ A, const __half* __restrict__ Bt,
                  __half* __restrict__ H0, float* __restrict__ C1,
                  int M, int ncut, int ld) {
    constexpr int K = KCHUNKS * 16;
    extern __shared__ __half sm[];
    __half* stage_base[3] = { sm, sm + HG_STAGE_ELEMS, sm + 2 * HG_STAGE_ELEMS };

    int t = threadIdx.x;
    int lane = t & 31, wid = t >> 5;
    int wm = wid & 1, wn = wid >> 1;          // 2 x 4 warp grid
    int group = lane >> 2, tig = lane & 3;
    int m0 = blockIdx.y * 128, n0 = blockIdx.x * 128;

    int a_row = lane & 15;
    int a_col = ((lane >> 4) & 1) * 8;
    int b_row = ((lane >> 4) & 1) * 8 + (lane & 7);
    int b_col = ((lane >> 3) & 1) * 8;

    float acc[4][4][4];
#pragma unroll
    for (int i = 0; i < 4; i++)
#pragma unroll
        for (int j = 0; j < 4; j++)
#pragma unroll
            for (int q = 0; q < 4; q++) acc[i][j][q] = 0.f;

    int lrow = t >> 1, lkq = (t & 1) * 8;
    int grow = m0 + lrow;
    int abytes = (grow < M) ? 16 : 0;
    const __half* pA = A + (size_t)(grow < M ? grow : 0) * K + lkq;
    const __half* pB = Bt + (size_t)(n0 + lrow) * K + lkq;
    int lofs = lrow * 24 + lkq;

    auto load_stage = [&](int c, int st) {
        __half* base = stage_base[st];
        int ko = c * 16;
        cp16(base + lofs,        pA + ko, abytes);
        cp16(base + 3072 + lofs, pB + ko, 16);
        cp_commit();
    };

    load_stage(0, 0);
    if (KCHUNKS > 1) load_stage(1, 1);

#pragma unroll
    for (int c = 0; c < KCHUNKS; c++) {
        if (c + 1 < KCHUNKS) cp_wait1(); else cp_wait0();
        __syncthreads();
        if (c + 2 < KCHUNKS) load_stage(c + 2, (c + 2) % 3);

        __half* base = stage_base[c % 3];
        __half* as = base;
        __half* bs = base + 3072;

        uint32_t af[4][4];
#pragma unroll
        for (int mf = 0; mf < 4; mf++) {
            int r0 = wm * 64 + mf * 16;
            ldsm4(af[mf], as + (r0 + a_row) * 24 + a_col);
        }
        uint32_t bf[2][4];
#pragma unroll
        for (int p = 0; p < 2; p++) {
            int c0 = wn * 32 + p * 16;
            ldsm4(bf[p], bs + (c0 + b_row) * 24 + b_col);
        }
#pragma unroll
        for (int nf = 0; nf < 4; nf++) {
            const uint32_t* bp = &bf[nf >> 1][(nf & 1) * 2];
#pragma unroll
            for (int mf = 0; mf < 4; mf++)
                mma_f16(acc[mf][nf], af[mf], bp);
        }
    }

#pragma unroll
    for (int mf = 0; mf < 4; mf++) {
        int r = m0 + wm * 64 + mf * 16 + group;
#pragma unroll
        for (int nf = 0; nf < 4; nf++) {
            int cc = n0 + wn * 32 + nf * 8 + tig * 2;
            if (cc < ncut) {
                if (r < M)
                    *(__half2*)&H0[(size_t)r * ld + cc] =
                        __floats2half2_rn(acc[mf][nf][0], acc[mf][nf][1]);
                if (r + 8 < M)
                    *(__half2*)&H0[(size_t)(r + 8) * ld + cc] =
                        __floats2half2_rn(acc[mf][nf][2], acc[mf][nf][3]);
            } else {
                int ccol = cc - ncut;
                if (r < M)
                    *(float2*)&C1[(size_t)r * ld + ccol] = make_float2(acc[mf][nf][0], acc[mf][nf][1]);
                if (r + 8 < M)
                    *(float2*)&C1[(size_t)(r + 8) * ld + ccol] = make_float2(acc[mf][nf][2], acc[mf][nf][3]);
            }
        }
    }
}

#define LRELU(v) ((v) > 0.f ? (v) : 0.2f * (v))

// unpack 8 halves (uint4) to 8 floats
__device__ __forceinline__ void h8_to_f8(uint4 raw, float f[8]) {
    float2 p0 = __half22float2(*(__half2*)&raw.x);
    float2 p1 = __half22float2(*(__half2*)&raw.y);
    float2 p2 = __half22float2(*(__half2*)&raw.z);
    float2 p3 = __half22float2(*(__half2*)&raw.w);
    f[0] = p0.x; f[1] = p0.y; f[2] = p1.x; f[3] = p1.y;
    f[4] = p2.x; f[5] = p2.y; f[6] = p3.x; f[7] = p3.y;
}

// ---------------- Layer 1 GAT (xl fp16) + fused fp16 convert of hidden -----
__global__ void gat1_kernel(const float* __restrict__ att1, const float* __restrict__ b1,
                            const float* __restrict__ lng, const float* __restrict__ lnb,
                            int Nn) {
    int i = blockIdx.x;
    int t = threadIdx.x;
    int h = t >> 5;
    int l = t & 31;
    int s = l >> 3;
    int c = l & 7;
    __shared__ float sout[256];
    __shared__ float red[4];
    __shared__ float red2[4];

    const float* xrp = g_xr1 + (size_t)i * L1C + h * 64 + c * 8;
    float4 xr0 = ((const float4*)xrp)[0];
    float4 xr1 = ((const float4*)xrp)[1];
    const float* atp = att1 + h * 64 + c * 8;
    float4 at0 = ((const float4*)atp)[0];
    float4 at1 = ((const float4*)atp)[1];
    float xr[8] = {xr0.x, xr0.y, xr0.z, xr0.w, xr1.x, xr1.y, xr1.z, xr1.w};
    float at[8] = {at0.x, at0.y, at0.z, at0.w, at1.x, at1.y, at1.z, at1.w};

    float acc[8] = {0.f, 0.f, 0.f, 0.f, 0.f, 0.f, 0.f, 0.f};
    float den = 0.f;
    int e0 = g_off[i], deg = g_off[i + 1] - e0;
    for (int base = 0; base < deg; base += 4) {
        int valid = (base + s) < deg;
        int j = valid ? __ldg(&g_src[e0 + base + s]) : 0;
        uint4 raw = *(const uint4*)(g_xlh + (size_t)j * 256 + h * 64 + c * 8);
        float xa[8];
        h8_to_f8(raw, xa);
        float term = 0.f;
#pragma unroll
        for (int k = 0; k < 8; k++) term += LRELU(xa[k] + xr[k]) * at[k];
        term += __shfl_xor_sync(0xffffffffu, term, 1);
        term += __shfl_xor_sync(0xffffffffu, term, 2);
        term += __shfl_xor_sync(0xffffffffu, term, 4);
        float a = valid ? __expf(term) : 0.f;
#pragma unroll
        for (int k = 0; k < 8; k++) acc[k] += a * xa[k];
        den += a;
    }
#pragma unroll
    for (int k = 0; k < 8; k++) {
        acc[k] += __shfl_xor_sync(0xffffffffu, acc[k], 8);
        acc[k] += __shfl_xor_sync(0xffffffffu, acc[k], 16);
    }
    den += __shfl_xor_sync(0xffffffffu, den, 8);
    den += __shfl_xor_sync(0xffffffffu, den, 16);
    float inv = 1.f / (den + 1e-16f);
    if (s == 0) {
#pragma unroll
        for (int k = 0; k < 8; k++) sout[h * 64 + c * 8 + k] = acc[k] * inv;
    }
    __syncthreads();

    int w = t >> 5, lane = t & 31;
    float val = 0.f;
    if (t < 64)
        val = 0.25f * (sout[t] + sout[t + 64] + sout[t + 128] + sout[t + 192]) + b1[t];

    float v = (t < 64) ? val : 0.f;
#pragma unroll
    for (int o = 16; o; o >>= 1) v += __shfl_xor_sync(0xffffffffu, v, o);
    if (lane == 0) red[w] = v;
    __syncthreads();
    float mu = (red[0] + red[1] + red[2] + red[3]) * (1.f / 64.f);
    float dd = (t < 64) ? (val - mu) : 0.f;
    float v2 = dd * dd;
#pragma unroll
    for (int o = 16; o; o >>= 1) v2 += __shfl_xor_sync(0xffffffffu, v2, o);
    if (lane == 0) red2[w] = v2;
    __syncthreads();
    float var = (red2[0] + red2[1] + red2[2] + red2[3]) * (1.f / 64.f);
    if (t < 64) {
        float y = dd * rsqrtf(var + 1e-5f) * lng[t] + lnb[t];
        float hv = fmaxf(y, 0.f);
        g_h[(size_t)i * HID + t] = hv;
        g_ah[(size_t)i * HID + t] = __float2half_rn(hv);
    }
}

// ---------------- Layer 2 GAT: xl2 fp16 (ld 64), warp per node -------------
__global__ void gat2_kernel(const float* __restrict__ att2, const float* __restrict__ b2,
                            const float* __restrict__ lng, const float* __restrict__ lnb,
                            float* __restrict__ out, int Nn) {
    int w = threadIdx.x >> 5, l = threadIdx.x & 31;
    int i = blockIdx.x * 4 + w;
    if (i >= Nn) return;
    int s = l >> 3;
    int c = l & 7;
    const float* xr2 = g_xr1;                  // layer2 xr overlay (fp32, ld 64)

    const float* xrp = xr2 + (size_t)i * OUTD + c * 8;
    float4 xr0 = ((const float4*)xrp)[0];
    float4 xr1 = ((const float4*)xrp)[1];
    const float* atp = att2 + c * 8;
    float4 at0 = ((const float4*)atp)[0];
    float4 at1 = ((const float4*)atp)[1];
    float xr[8] = {xr0.x, xr0.y, xr0.z, xr0.w, xr1.x, xr1.y, xr1.z, xr1.w};
    float at[8] = {at0.x, at0.y, at0.z, at0.w, at1.x, at1.y, at1.z, at1.w};

    float acc[8] = {0.f, 0.f, 0.f, 0.f, 0.f, 0.f, 0.f, 0.f};
    float den = 0.f;
    int e0 = g_off[i], deg = g_off[i + 1] - e0;
    for (int base = 0; base < deg; base += 4) {
        int valid = (base + s) < deg;
        int j = valid ? __ldg(&g_src[e0 + base + s]) : 0;
        uint4 raw = *(const uint4*)(g_xlh + (size_t)j * OUTD + c * 8);
        float xa[8];
        h8_to_f8(raw, xa);
        float term = 0.f;
#pragma unroll
        for (int k = 0; k < 8; k++) term += LRELU(xa[k] + xr[k]) * at[k];
        term += __shfl_xor_sync(0xffffffffu, term, 1);
        term += __shfl_xor_sync(0xffffffffu, term, 2);
        term += __shfl_xor_sync(0xffffffffu, term, 4);
        float a = valid ? __expf(term) : 0.f;
#pragma unroll
        for (int k = 0; k < 8; k++) acc[k] += a * xa[k];
        den += a;
    }
#pragma unroll
    for (int k = 0; k < 8; k++) {
        acc[k] += __shfl_xor_sync(0xffffffffu, acc[k], 8);
        acc[k] += __shfl_xor_sync(0xffffffffu, acc[k], 16);
    }
    den += __shfl_xor_sync(0xffffffffu, den, 8);
    den += __shfl_xor_sync(0xffffffffu, den, 16);
    float inv = 1.f / (den + 1e-16f);

    const float* bp = b2 + c * 8;
    float4 bb0 = ((const float4*)bp)[0];
    float4 bb1 = ((const float4*)bp)[1];
    float bb[8] = {bb0.x, bb0.y, bb0.z, bb0.w, bb1.x, bb1.y, bb1.z, bb1.w};
    float v[8];
#pragma unroll
    for (int k = 0; k < 8; k++) v[k] = acc[k] * inv + bb[k];

    float sum = v[0] + v[1] + v[2] + v[3] + v[4] + v[5] + v[6] + v[7];
#pragma unroll
    for (int o = 16; o; o >>= 1) sum += __shfl_xor_sync(0xffffffffu, sum, o);
    float mu = sum * (1.f / 256.f);
    float q = 0.f;
    float d[8];
#pragma unroll
    for (int k = 0; k < 8; k++) { d[k] = v[k] - mu; q += d[k] * d[k]; }
#pragma unroll
    for (int o = 16; o; o >>= 1) q += __shfl_xor_sync(0xffffffffu, q, o);
    float var = q * (1.f / 256.f);
    float r = rsqrtf(var + 1e-5f);
    if (s == 0) {
        const float* gp = lng + c * 8;
        const float* np = lnb + c * 8;
        float4 gg0 = ((const float4*)gp)[0], gg1 = ((const float4*)gp)[1];
        float4 nn0 = ((const float4*)np)[0], nn1 = ((const float4*)np)[1];
        float4 o0, o1;
        o0.x = d[0] * r * gg0.x + nn0.x; o0.y = d[1] * r * gg0.y + nn0.y;
        o0.z = d[2] * r * gg0.z + nn0.z; o0.w = d[3] * r * gg0.w + nn0.w;
        o1.x = d[4] * r * gg1.x + nn1.x; o1.y = d[5] * r * gg1.y + nn1.y;
        o1.z = d[6] * r * gg1.z + nn1.z; o1.w = d[7] * r * gg1.w + nn1.w;
        float* op = out + (size_t)i * OUTD + c * 8;
        ((float4*)op)[0] = o0;
        ((float4*)op)[1] = o1;
    }
}

// ---------------- launch ----------------
extern "C" void kernel_launch(void* const* d_in, const int* in_sizes, int n_in,
                              void* d_out, int out_size) {
    const float* x    = (const float*)d_in[0];
    const int*   ei   = (const int*)d_in[1];
    const float* W1l  = (const float*)d_in[2];
    const float* W1r  = (const float*)d_in[3];
    const float* att1 = (const float*)d_in[4];
    const float* b1   = (const float*)d_in[5];
    const float* ln1g = (const float*)d_in[6];
    const float* ln1b = (const float*)d_in[7];
    const float* W2l  = (const float*)d_in[8];
    const float* W2r  = (const float*)d_in[9];
    const float* att2 = (const float*)d_in[10];
    const float* b2   = (const float*)d_in[11];
    const float* ln2g = (const float*)d_in[12];
    const float* ln2b = (const float*)d_in[13];
    float* out = (float*)d_out;

    int N = in_sizes[0] / IN_DIM;
    int E = in_sizes[1] / 2;
    if (N > NMAX) N = NMAX;
    if (E > EMAX) E = EMAX;
    int ETOT_RT = E + N;
    int nscan = (N + SCAN_BLK - 1) / SCAN_BLK;

    float *p_xr1, *p_h;
    __half *p_xlh, *p_ah, *p_bh, *p_bh2;
    cudaGetSymbolAddress((void**)&p_xr1, g_xr1);
    cudaGetSymbolAddress((void**)&p_h,   g_h);
    cudaGetSymbolAddress((void**)&p_xlh, g_xlh);
    cudaGetSymbolAddress((void**)&p_ah,  g_ah);
    cudaGetSymbolAddress((void**)&p_bh,  g_bh);
    cudaGetSymbolAddress((void**)&p_bh2, g_bh2);

    cudaFuncSetAttribute(hgemm_kernel<16>, cudaFuncAttributeMaxDynamicSharedMemorySize, HG_SMEM_BYTES);
    cudaFuncSetAttribute(hgemm_kernel<4>,  cudaFuncAttributeMaxDynamicSharedMemorySize, HG_SMEM_BYTES);

    static cudaStream_t s2 = nullptr;
    static cudaEvent_t ev_fork = nullptr, ev_g1 = nullptr;
    if (!s2) {
        cudaStreamCreateWithFlags(&s2, cudaStreamNonBlocking);
        cudaEventCreateWithFlags(&ev_fork, cudaEventDisableTiming);
        cudaEventCreateWithFlags(&ev_g1, cudaEventDisableTiming);
    }

    cudaEventRecord(ev_fork, 0);
    cudaStreamWaitEvent(s2, ev_fork, 0);

    // ---- stream s2: layer-1 GEMM chain (fp16; xl1 -> fp16, xr1 -> fp32) ----
    {
        int n4 = N * IN_DIM / 4;
        conv_h_kernel<<<(n4 + 255) / 256, 256, 0, s2>>>(x, p_ah, n4);
        pack_bt_h_kernel<<<(512 * 256 + 255) / 256, 256, 0, s2>>>(W1l, W1r, p_bh, 256, 256);
        pack_bt_h_kernel<<<(128 * 64 + 255) / 256, 256, 0, s2>>>(W2l, W2r, p_bh2, 64, 64);
        dim3 grid(4, (N + 127) / 128);
        hgemm_kernel<16><<<grid, 256, HG_SMEM_BYTES, s2>>>(p_ah, p_bh, p_xlh, p_xr1, N, 256, 256);
        cudaEventRecord(ev_g1, s2);
    }

    // ---- default stream: CSR build (concurrent) ----
    zero_deg_kernel<<<(N + 256) / 256, 256>>>(N);
    hist_kernel<<<(ETOT_RT + 255) / 256, 256>>>(ei, E, N);
    scan1_kernel<<<nscan, SCAN_BLK>>>(N);
    scan2_kernel<<<1, 64>>>(nscan, N);
    scan3_kernel<<<nscan, SCAN_BLK>>>(N);
    scatter_kernel<<<(ETOT_RT + 255) / 256, 256>>>(ei, E, N);

    cudaStreamWaitEvent(0, ev_g1, 0);

    gat1_kernel<<<N, 128>>>(att1, b1, ln1g, ln1b, N);

    // Layer 2 GEMM: xl2 -> fp16 (g_xlh, ld 64), xr2 -> fp32 (g_xr1, ld 64)
    {
        dim3 grid(1, (N + 127) / 128);
        hgemm_kernel<4><<<grid, 256, HG_SMEM_BYTES>>>(p_ah, p_bh2, p_xlh, p_xr1, N, 64, 64);
    }

    gat2_kernel<<<(N + 3) / 4, 128>>>(att2, b2, ln2g, ln2b, out, N);
}